// round 5
// baseline (speedup 1.0000x reference)
#include <cuda_runtime.h>
#include <cuda_bf16.h>
#include <math_constants.h>

#define N_NODES 100000
#define N_EDGES 1600000
#define IN_FEATS 256
#define HID 128

typedef unsigned long long u64;

// ---------------- device scratch (static, allocation-free) ----------------
__device__ float g_h[N_NODES * HID];      // h of current layer (reused)
__device__ float g_x2[N_NODES * HID];     // elu(layer1 out) = layer2 input
__device__ float g_el[N_NODES];
__device__ float g_er[N_NODES];
__device__ float g_s[N_NODES];            // softmax denominators
__device__ float g_w[N_EDGES];            // per-edge exp weights (CSR order)
__device__ int   g_rowptr[N_NODES + 1];
__device__ int   g_cnt[N_NODES + 1];      // counts, then cursor
__device__ int   g_csrc[N_EDGES];         // src node per CSR slot

// ---------------- f32x2 helpers ----------------
__device__ __forceinline__ u64 ffma2(u64 a, u64 b, u64 c) {
    u64 d;
    asm("fma.rn.f32x2 %0, %1, %2, %3;" : "=l"(d) : "l"(a), "l"(b), "l"(c));
    return d;
}
__device__ __forceinline__ float lo2(u64 v) { return __uint_as_float((unsigned)v); }
__device__ __forceinline__ float hi2(u64 v) { return __uint_as_float((unsigned)(v >> 32)); }

// ---------------- CSR build ----------------
__global__ void hist_kernel(const int* __restrict__ dst, int* __restrict__ cnt, int e) {
    int i = blockIdx.x * blockDim.x + threadIdx.x;
    if (i < e) atomicAdd(&cnt[dst[i]], 1);
}

__global__ void scan_kernel(int* __restrict__ cnt, int* __restrict__ rowptr, int n) {
    __shared__ int ts[1024];
    int tid = threadIdx.x;
    int chunk = (n + 1023) / 1024;
    int lo = tid * chunk;
    int hi = lo + chunk; if (hi > n) hi = n; if (lo > n) lo = n;
    int sum = 0;
    for (int i = lo; i < hi; i++) sum += cnt[i];
    ts[tid] = sum;
    __syncthreads();
    for (int off = 1; off < 1024; off <<= 1) {
        int add = (tid >= off) ? ts[tid - off] : 0;
        __syncthreads();
        ts[tid] += add;
        __syncthreads();
    }
    int excl = ts[tid] - sum;
    int run = excl;
    for (int i = lo; i < hi; i++) {
        int c = cnt[i];
        rowptr[i] = run;
        cnt[i] = run;   // cursor
        run += c;
    }
    if (tid == 1023) rowptr[n] = run;
}

__global__ void fill_kernel(const int* __restrict__ src, const int* __restrict__ dst,
                            int* __restrict__ cursor, int* __restrict__ csrc, int e) {
    int i = blockIdx.x * blockDim.x + threadIdx.x;
    if (i < e) {
        int d = dst[i];
        int p = atomicAdd(&cursor[d], 1);
        csrc[p] = src[i];
    }
}

// ---------------- fused GEMM (h = X @ W^T) + el/er epilogue ----------------
// block = 256 threads, tile = 64 nodes x 128 cols, K-chunks of 32.
// FFMA2 (fp32x2) inner loop: accumulators packed pairwise along the node dim.
// W stored duplicated in smem so LDS.64 yields {w,w} pairs directly.
template <int K>
__global__ void __launch_bounds__(256, 2)
gemm_kernel(const float* __restrict__ X, const float* __restrict__ W,
            const float* __restrict__ al, const float* __restrict__ ar,
            float* __restrict__ H, float* __restrict__ el, float* __restrict__ er,
            int nnodes)
{
    constexpr int KC = 32;
    constexpr int WROW = 266;       // 256 dup floats + pad (even, 2-way STS conflict max)
    __shared__ float Xs[KC][68];    // [k][node], 16B-aligned rows
    __shared__ float Wsdup[KC][WROW];
    const int node0 = blockIdx.x * 64;
    const int tid = threadIdx.x;
    const int lane = tid & 31;      // col group: cols [4*lane, 4*lane+4)
    const int warp = tid >> 5;      // node group: nodes [node0+8*warp, +8)

    // loader coords (lane = kk, warp = col/node sub-block)
    const int kk_ld = lane;
    const int c0 = warp;            // W col base
    const int n0 = warp;            // X node base
    const int ow = (c0 & 3) * 64 + (c0 >> 2) * 2;   // dup-layout base offset

    u64 acc2[4][4];
#pragma unroll
    for (int np = 0; np < 4; np++)
#pragma unroll
        for (int c = 0; c < 4; c++) acc2[np][c] = 0ull;

    float wreg[16], xreg[8];

    // prefetch chunk 0
#pragma unroll
    for (int p = 0; p < 16; p++)
        wreg[p] = W[(c0 + p * 8) * K + kk_ld];
#pragma unroll
    for (int p = 0; p < 8; p++) {
        int node = node0 + n0 + p * 8;
        if (node >= nnodes) node = nnodes - 1;
        xreg[p] = X[node * K + kk_ld];
    }

    for (int k0 = 0; k0 < K; k0 += KC) {
        // store prefetched chunk to smem (W duplicated pairwise)
#pragma unroll
        for (int p = 0; p < 16; p++) {
            int o = ow + 4 * p;
            Wsdup[kk_ld][o]     = wreg[p];
            Wsdup[kk_ld][o + 1] = wreg[p];
        }
#pragma unroll
        for (int p = 0; p < 8; p++)
            Xs[kk_ld][n0 + p * 8] = xreg[p];
        __syncthreads();

        // prefetch next chunk while computing
        if (k0 + KC < K) {
#pragma unroll
            for (int p = 0; p < 16; p++)
                wreg[p] = W[(c0 + p * 8) * K + k0 + KC + kk_ld];
#pragma unroll
            for (int p = 0; p < 8; p++) {
                int node = node0 + n0 + p * 8;
                if (node >= nnodes) node = nnodes - 1;
                xreg[p] = X[node * K + k0 + KC + kk_ld];
            }
        }

#pragma unroll
        for (int kk = 0; kk < KC; kk++) {
            // W dup pairs: conflict-free LDS.64 (lane stride 8B over 16-lane phase)
            u64 wd0 = *(const u64*)&Wsdup[kk][0 * 64 + 2 * lane];
            u64 wd1 = *(const u64*)&Wsdup[kk][1 * 64 + 2 * lane];
            u64 wd2 = *(const u64*)&Wsdup[kk][2 * 64 + 2 * lane];
            u64 wd3 = *(const u64*)&Wsdup[kk][3 * 64 + 2 * lane];
            // X node pairs: broadcast LDS.128 reinterpreted as u64 pairs
            ulonglong2 xa = *(const ulonglong2*)&Xs[kk][warp * 8];
            ulonglong2 xb = *(const ulonglong2*)&Xs[kk][warp * 8 + 4];
            u64 xp[4] = {xa.x, xa.y, xb.x, xb.y};
#pragma unroll
            for (int np = 0; np < 4; np++) {
                acc2[np][0] = ffma2(xp[np], wd0, acc2[np][0]);
                acc2[np][1] = ffma2(xp[np], wd1, acc2[np][1]);
                acc2[np][2] = ffma2(xp[np], wd2, acc2[np][2]);
                acc2[np][3] = ffma2(xp[np], wd3, acc2[np][3]);
            }
        }
        __syncthreads();
    }

    // unpack accumulators: acc[n][c], n = 2*np + half
    float acc[8][4];
#pragma unroll
    for (int np = 0; np < 4; np++)
#pragma unroll
        for (int c = 0; c < 4; c++) {
            acc[2 * np][c]     = lo2(acc2[np][c]);
            acc[2 * np + 1][c] = hi2(acc2[np][c]);
        }

    // epilogue: store h rows + warp-reduced el/er
    float4 al4 = *(const float4*)&al[lane * 4];
    float4 ar4 = *(const float4*)&ar[lane * 4];
#pragma unroll
    for (int n = 0; n < 8; n++) {
        int node = node0 + warp * 8 + n;
        bool valid = node < nnodes;
        if (valid) {
            float4 hv = make_float4(acc[n][0], acc[n][1], acc[n][2], acc[n][3]);
            *(float4*)&H[node * HID + lane * 4] = hv;
        }
        float sl = acc[n][0] * al4.x + acc[n][1] * al4.y + acc[n][2] * al4.z + acc[n][3] * al4.w;
        float sr = acc[n][0] * ar4.x + acc[n][1] * ar4.y + acc[n][2] * ar4.z + acc[n][3] * ar4.w;
#pragma unroll
        for (int off = 16; off; off >>= 1) {
            sl += __shfl_xor_sync(0xffffffffu, sl, off);
            sr += __shfl_xor_sync(0xffffffffu, sr, off);
        }
        if (valid && lane == 0) { el[node] = sl; er[node] = sr; }
    }
}

// ---------------- per-node softmax (one warp per dst node) ----------------
__global__ void attn_kernel(const int* __restrict__ rowptr, const int* __restrict__ csrc,
                            const float* __restrict__ el, const float* __restrict__ er,
                            float* __restrict__ w, float* __restrict__ s, int n)
{
    int gw = (blockIdx.x * blockDim.x + threadIdx.x) >> 5;
    int lane = threadIdx.x & 31;
    if (gw >= n) return;
    int lo = rowptr[gw], hi = rowptr[gw + 1];
    float erd = er[gw];
    float mx = -CUDART_INF_F;
    for (int j = lo + lane; j < hi; j += 32) {
        float e = el[csrc[j]] + erd;
        e = e > 0.f ? e : 0.2f * e;     // leaky_relu, slope 0.2
        w[j] = e;
        mx = fmaxf(mx, e);
    }
#pragma unroll
    for (int off = 16; off; off >>= 1)
        mx = fmaxf(mx, __shfl_xor_sync(0xffffffffu, mx, off));
    float sum = 0.f;
    for (int j = lo + lane; j < hi; j += 32) {
        float ex = __expf(w[j] - mx);
        w[j] = ex;
        sum += ex;
    }
#pragma unroll
    for (int off = 16; off; off >>= 1)
        sum += __shfl_xor_sync(0xffffffffu, sum, off);
    if (lane == 0) s[gw] = sum;
}

// ---------------- weighted gather-aggregate (one warp per dst node) ----------------
template <bool ELU>
__global__ void agg_kernel(const int* __restrict__ rowptr, const int* __restrict__ csrc,
                           const float* __restrict__ w, const float* __restrict__ s,
                           const float* __restrict__ h, const float* __restrict__ bias,
                           float* __restrict__ out, int n)
{
    int gw = (blockIdx.x * blockDim.x + threadIdx.x) >> 5;
    int lane = threadIdx.x & 31;
    if (gw >= n) return;
    int lo = rowptr[gw], hi = rowptr[gw + 1];
    const float4* __restrict__ h4 = (const float4*)h;
    float4 acc0 = make_float4(0.f, 0.f, 0.f, 0.f);
    float4 acc1 = make_float4(0.f, 0.f, 0.f, 0.f);
    int j = lo;
    for (; j + 1 < hi; j += 2) {
        int s0 = __ldg(&csrc[j]);
        int s1 = __ldg(&csrc[j + 1]);
        float w0 = __ldg(&w[j]);
        float w1 = __ldg(&w[j + 1]);
        float4 h0 = __ldg(&h4[s0 * 32 + lane]);
        float4 h1 = __ldg(&h4[s1 * 32 + lane]);
        acc0.x = fmaf(w0, h0.x, acc0.x);
        acc0.y = fmaf(w0, h0.y, acc0.y);
        acc0.z = fmaf(w0, h0.z, acc0.z);
        acc0.w = fmaf(w0, h0.w, acc0.w);
        acc1.x = fmaf(w1, h1.x, acc1.x);
        acc1.y = fmaf(w1, h1.y, acc1.y);
        acc1.z = fmaf(w1, h1.z, acc1.z);
        acc1.w = fmaf(w1, h1.w, acc1.w);
    }
    if (j < hi) {
        int s0 = __ldg(&csrc[j]);
        float w0 = __ldg(&w[j]);
        float4 h0 = __ldg(&h4[s0 * 32 + lane]);
        acc0.x = fmaf(w0, h0.x, acc0.x);
        acc0.y = fmaf(w0, h0.y, acc0.y);
        acc0.z = fmaf(w0, h0.z, acc0.z);
        acc0.w = fmaf(w0, h0.w, acc0.w);
    }
    float4 acc = make_float4(acc0.x + acc1.x, acc0.y + acc1.y,
                             acc0.z + acc1.z, acc0.w + acc1.w);
    float sv = s[gw];
    float inv = sv > 0.f ? 1.f / sv : 0.f;
    float4 b4 = ((const float4*)bias)[lane];
    float4 r;
    r.x = fmaf(acc.x, inv, b4.x);
    r.y = fmaf(acc.y, inv, b4.y);
    r.z = fmaf(acc.z, inv, b4.z);
    r.w = fmaf(acc.w, inv, b4.w);
    if (ELU) {
        r.x = r.x > 0.f ? r.x : __expf(r.x) - 1.f;
        r.y = r.y > 0.f ? r.y : __expf(r.y) - 1.f;
        r.z = r.z > 0.f ? r.z : __expf(r.z) - 1.f;
        r.w = r.w > 0.f ? r.w : __expf(r.w) - 1.f;
    }
    ((float4*)out)[gw * 32 + lane] = r;
}

// ---------------- launch ----------------
extern "C" void kernel_launch(void* const* d_in, const int* in_sizes, int n_in,
                              void* d_out, int out_size)
{
    const float* features = (const float*)d_in[0];
    const int*   src      = (const int*)d_in[1];
    const int*   dst      = (const int*)d_in[2];
    const float* W1       = (const float*)d_in[3];
    const float* al1      = (const float*)d_in[4];
    const float* ar1      = (const float*)d_in[5];
    const float* b1       = (const float*)d_in[6];
    const float* W2       = (const float*)d_in[7];
    const float* al2      = (const float*)d_in[8];
    const float* ar2      = (const float*)d_in[9];
    const float* b2       = (const float*)d_in[10];
    float* out = (float*)d_out;

    const int n = in_sizes[0] / IN_FEATS;   // 100000
    const int e = in_sizes[1];              // 1600000

    float *h, *x2, *el, *er, *sarr, *warr;
    int *rowptr, *cnt, *csrc;
    cudaGetSymbolAddress((void**)&h,      g_h);
    cudaGetSymbolAddress((void**)&x2,     g_x2);
    cudaGetSymbolAddress((void**)&el,     g_el);
    cudaGetSymbolAddress((void**)&er,     g_er);
    cudaGetSymbolAddress((void**)&sarr,   g_s);
    cudaGetSymbolAddress((void**)&warr,   g_w);
    cudaGetSymbolAddress((void**)&rowptr, g_rowptr);
    cudaGetSymbolAddress((void**)&cnt,    g_cnt);
    cudaGetSymbolAddress((void**)&csrc,   g_csrc);

    const int TPB = 256;
    const int eblocks = (e + TPB - 1) / TPB;
    const int nwarp_blocks = (n * 32 + TPB - 1) / TPB;
    const int gemm_blocks = (n + 63) / 64;

    // CSR build (by dst)
    cudaMemsetAsync(cnt, 0, (size_t)(n + 1) * sizeof(int));
    hist_kernel<<<eblocks, TPB>>>(dst, cnt, e);
    scan_kernel<<<1, 1024>>>(cnt, rowptr, n);
    fill_kernel<<<eblocks, TPB>>>(src, dst, cnt, csrc, e);

    // ---- layer 1 ----
    gemm_kernel<IN_FEATS><<<gemm_blocks, TPB>>>(features, W1, al1, ar1, h, el, er, n);
    attn_kernel<<<nwarp_blocks, TPB>>>(rowptr, csrc, el, er, warr, sarr, n);
    agg_kernel<true><<<nwarp_blocks, TPB>>>(rowptr, csrc, warr, sarr, h, b1, x2, n);

    // ---- layer 2 ----
    gemm_kernel<HID><<<gemm_blocks, TPB>>>(x2, W2, al2, ar2, h, el, er, n);
    attn_kernel<<<nwarp_blocks, TPB>>>(rowptr, csrc, el, er, warr, sarr, n);
    agg_kernel<false><<<nwarp_blocks, TPB>>>(rowptr, csrc, warr, sarr, h, b2, out, n);
}

// round 8
// speedup vs baseline: 1.2316x; 1.2316x over previous
#include <cuda_runtime.h>
#include <cuda_bf16.h>
#include <math_constants.h>
#include <cstdint>

#define N_NODES 100000
#define N_EDGES 1600000
#define IN_FEATS 256
#define HID 128

typedef unsigned long long u64;

// ---------------- device scratch (static, allocation-free) ----------------
__device__ float g_h[N_NODES * HID];
__device__ float g_x2[N_NODES * HID];
__device__ float g_el[N_NODES];
__device__ float g_er[N_NODES];
__device__ float g_s[N_NODES];
__device__ float g_w[N_EDGES];
__device__ int   g_rowptr[N_NODES + 1];
__device__ int   g_cnt[N_NODES + 1];
__device__ int   g_csrc[N_EDGES];

// ---------------- portable tensor-op helpers (sm_80+ PTX, valid on sm_103) ----
__device__ __forceinline__ uint32_t smem_u32(const void* p) {
    return (uint32_t)__cvta_generic_to_shared(p);
}
__device__ __forceinline__ void ldsm_x4(uint32_t* r, uint32_t addr) {
    asm volatile("ldmatrix.sync.aligned.m8n8.x4.shared.b16 {%0,%1,%2,%3}, [%4];"
                 : "=r"(r[0]), "=r"(r[1]), "=r"(r[2]), "=r"(r[3]) : "r"(addr));
}
__device__ __forceinline__ void ldsm_x2(uint32_t* r, uint32_t addr) {
    asm volatile("ldmatrix.sync.aligned.m8n8.x2.shared.b16 {%0,%1}, [%2];"
                 : "=r"(r[0]), "=r"(r[1]) : "r"(addr));
}
__device__ __forceinline__ void mma_bf16(float* d, const uint32_t* a, const uint32_t* b) {
    asm volatile(
        "mma.sync.aligned.m16n8k16.row.col.f32.bf16.bf16.f32 "
        "{%0,%1,%2,%3}, {%4,%5,%6,%7}, {%8,%9}, {%0,%1,%2,%3};"
        : "+f"(d[0]), "+f"(d[1]), "+f"(d[2]), "+f"(d[3])
        : "r"(a[0]), "r"(a[1]), "r"(a[2]), "r"(a[3]), "r"(b[0]), "r"(b[1]));
}
__device__ __forceinline__ uint32_t sw128(uint32_t off) {
    return off ^ ((off >> 3) & 0x70);
}

// convert float4 -> bf16 hi/lo pairs and store (8B each) into swizzled tiles
__device__ __forceinline__ void stage_f4(char* tileH, char* tileL,
                                         int row, int k4, float4 v) {
    __nv_bfloat16 h0 = __float2bfloat16_rn(v.x);
    __nv_bfloat16 h1 = __float2bfloat16_rn(v.y);
    __nv_bfloat16 h2 = __float2bfloat16_rn(v.z);
    __nv_bfloat16 h3 = __float2bfloat16_rn(v.w);
    __nv_bfloat16 l0 = __float2bfloat16_rn(v.x - __bfloat162float(h0));
    __nv_bfloat16 l1 = __float2bfloat16_rn(v.y - __bfloat162float(h1));
    __nv_bfloat16 l2 = __float2bfloat16_rn(v.z - __bfloat162float(h2));
    __nv_bfloat16 l3 = __float2bfloat16_rn(v.w - __bfloat162float(h3));
    uint32_t hA = (uint32_t)__bfloat16_as_ushort(h0) | ((uint32_t)__bfloat16_as_ushort(h1) << 16);
    uint32_t hB = (uint32_t)__bfloat16_as_ushort(h2) | ((uint32_t)__bfloat16_as_ushort(h3) << 16);
    uint32_t lA = (uint32_t)__bfloat16_as_ushort(l0) | ((uint32_t)__bfloat16_as_ushort(l1) << 16);
    uint32_t lB = (uint32_t)__bfloat16_as_ushort(l2) | ((uint32_t)__bfloat16_as_ushort(l3) << 16);
    uint32_t sw = sw128((uint32_t)(row * 128 + k4 * 2));
    *(uint2*)(tileH + sw) = make_uint2(hA, hB);
    *(uint2*)(tileL + sw) = make_uint2(lA, lB);
}

// ---------------- CSR build ----------------
__global__ void hist_kernel(const int* __restrict__ dst, int* __restrict__ cnt, int e) {
    int i = blockIdx.x * blockDim.x + threadIdx.x;
    if (i < e) atomicAdd(&cnt[dst[i]], 1);
}

__global__ void scan_kernel(int* __restrict__ cnt, int* __restrict__ rowptr, int n) {
    __shared__ int ts[1024];
    int tid = threadIdx.x;
    int chunk = (n + 1023) / 1024;
    int lo = tid * chunk;
    int hi = lo + chunk; if (hi > n) hi = n; if (lo > n) lo = n;
    int sum = 0;
    for (int i = lo; i < hi; i++) sum += cnt[i];
    ts[tid] = sum;
    __syncthreads();
    for (int off = 1; off < 1024; off <<= 1) {
        int add = (tid >= off) ? ts[tid - off] : 0;
        __syncthreads();
        ts[tid] += add;
        __syncthreads();
    }
    int excl = ts[tid] - sum;
    int run = excl;
    for (int i = lo; i < hi; i++) {
        int c = cnt[i];
        rowptr[i] = run;
        cnt[i] = run;
        run += c;
    }
    if (tid == 1023) rowptr[n] = run;
}

__global__ void fill_kernel(const int* __restrict__ src, const int* __restrict__ dst,
                            int* __restrict__ cursor, int* __restrict__ csrc, int e) {
    int i = blockIdx.x * blockDim.x + threadIdx.x;
    if (i < e) {
        int d = dst[i];
        int p = atomicAdd(&cursor[d], 1);
        csrc[p] = src[i];
    }
}

// ---------------- mma.sync GEMM: H = X @ W^T (+ fused el/er epilogue) --------
// CTA tile: 128 nodes x 128 cols, 8 warps (4x2), warp tile m32 x n64.
// K-chunks of 64, SW128 smem. 3-pass bf16 split: D += Ah*Bh + Al*Bh + Ah*Bl.
template <int K>
__global__ void __launch_bounds__(256)
gemm_mma(const float* __restrict__ X, const float* __restrict__ W,
         const float* __restrict__ al, const float* __restrict__ ar,
         float* __restrict__ H, float* __restrict__ el, float* __restrict__ er,
         int nnodes)
{
    extern __shared__ char smem_raw[];
    char* tiles = (char*)(((uintptr_t)smem_raw + 1023) & ~(uintptr_t)1023);
    char* tAH = tiles;
    char* tAL = tiles + 16384;
    char* tBH = tiles + 32768;
    char* tBL = tiles + 49152;
    const uint32_t aAH = smem_u32(tAH);
    const uint32_t aAL = smem_u32(tAL);
    const uint32_t aBH = smem_u32(tBH);
    const uint32_t aBL = smem_u32(tBL);

    const int tid  = threadIdx.x;
    const int lane = tid & 31;
    const int wid  = tid >> 5;
    const int node0 = blockIdx.x * 128;
    const int m0 = (wid >> 1) * 32;    // warp row base   (4 groups)
    const int n0 = (wid & 1) * 64;     // warp col base   (2 groups)

    // ldmatrix lane geometry
    const int arow = lane & 15;
    const uint32_t acol = ((lane >> 4) & 1) * 16;   // bytes
    const int brow = lane & 7;
    const uint32_t bcol = ((lane >> 3) & 1) * 16;   // bytes (lanes 0-15 matter for x2)

    float d[2][8][4];
#pragma unroll
    for (int at = 0; at < 2; at++)
#pragma unroll
        for (int nt = 0; nt < 8; nt++)
#pragma unroll
            for (int i = 0; i < 4; i++) d[at][nt][i] = 0.f;

    constexpr int NCH = K / 64;
#pragma unroll
    for (int c = 0; c < NCH; c++) {
        const int k0 = c * 64;
        // stage A (X rows = nodes): 128 rows x 16 float4; 8 float4/thread
#pragma unroll
        for (int i = 0; i < 8; i++) {
            int gi = tid + i * 256;
            int row = gi >> 4;
            int k4 = (gi & 15) * 4;
            int node = node0 + row;
            if (node >= nnodes) node = nnodes - 1;
            float4 v = *(const float4*)(X + (size_t)node * K + k0 + k4);
            stage_f4(tAH, tAL, row, k4, v);
        }
        // stage B (W rows = out cols): 128 rows x 16 float4
#pragma unroll
        for (int i = 0; i < 8; i++) {
            int gi = tid + i * 256;
            int row = gi >> 4;
            int k4 = (gi & 15) * 4;
            float4 v = *(const float4*)(W + (size_t)row * K + k0 + k4);
            stage_f4(tBH, tBL, row, k4, v);
        }
        __syncthreads();

#pragma unroll
        for (int s = 0; s < 4; s++) {
            const uint32_t sb = (uint32_t)(s * 32);
            uint32_t ah[2][4], alo[2][4], bh[8][2], blo[8][2];
#pragma unroll
            for (int at = 0; at < 2; at++) {
                int row = m0 + at * 16 + arow;
                uint32_t sw = sw128((uint32_t)(row * 128) + sb + acol);
                ldsm_x4(ah[at],  aAH + sw);
                ldsm_x4(alo[at], aAL + sw);
            }
#pragma unroll
            for (int nt = 0; nt < 8; nt++) {
                int row = n0 + nt * 8 + brow;
                uint32_t sw = sw128((uint32_t)(row * 128) + sb + bcol);
                ldsm_x2(bh[nt],  aBH + sw);
                ldsm_x2(blo[nt], aBL + sw);
            }
#pragma unroll
            for (int at = 0; at < 2; at++)
#pragma unroll
                for (int nt = 0; nt < 8; nt++) {
                    mma_bf16(d[at][nt], ah[at],  bh[nt]);
                    mma_bf16(d[at][nt], alo[at], bh[nt]);
                    mma_bf16(d[at][nt], ah[at],  blo[nt]);
                }
        }
        __syncthreads();
    }

    // ---- epilogue: stage C to smem, then coalesced writes + fused el/er ----
    float* cs = (float*)tiles;           // 128 x 132 fp32
#pragma unroll
    for (int at = 0; at < 2; at++) {
        int r0 = m0 + at * 16 + (lane >> 2);
#pragma unroll
        for (int nt = 0; nt < 8; nt++) {
            int cc = n0 + nt * 8 + (lane & 3) * 2;
            *(float2*)&cs[r0 * 132 + cc]       = make_float2(d[at][nt][0], d[at][nt][1]);
            *(float2*)&cs[(r0 + 8) * 132 + cc] = make_float2(d[at][nt][2], d[at][nt][3]);
        }
    }
    __syncthreads();
    {
        int row  = tid >> 1;
        int half = tid & 1;
        int node = node0 + row;
        bool valid = node < nnodes;
        float sl = 0.f, sr = 0.f;
        const float* crow = &cs[row * 132 + half * 64];
        if (valid) {
            float* hp = H + (size_t)node * HID + half * 64;
#pragma unroll
            for (int i = 0; i < 16; i++) {
                float4 v  = *(const float4*)(crow + 4 * i);
                float4 a4 = *(const float4*)(al + half * 64 + 4 * i);
                float4 r4 = *(const float4*)(ar + half * 64 + 4 * i);
                sl += v.x * a4.x + v.y * a4.y + v.z * a4.z + v.w * a4.w;
                sr += v.x * r4.x + v.y * r4.y + v.z * r4.z + v.w * r4.w;
                *(float4*)(hp + 4 * i) = v;
            }
        }
        sl += __shfl_xor_sync(0xffffffffu, sl, 1);
        sr += __shfl_xor_sync(0xffffffffu, sr, 1);
        if (valid && half == 0) { el[node] = sl; er[node] = sr; }
    }
}

// ---------------- per-node softmax (one warp per dst node) ----------------
__global__ void attn_kernel(const int* __restrict__ rowptr, const int* __restrict__ csrc,
                            const float* __restrict__ el, const float* __restrict__ er,
                            float* __restrict__ w, float* __restrict__ s, int n)
{
    int gw = (blockIdx.x * blockDim.x + threadIdx.x) >> 5;
    int lane = threadIdx.x & 31;
    if (gw >= n) return;
    int lo = rowptr[gw], hi = rowptr[gw + 1];
    float erd = er[gw];
    float mx = -CUDART_INF_F;
    for (int j = lo + lane; j < hi; j += 32) {
        float e = el[csrc[j]] + erd;
        e = e > 0.f ? e : 0.2f * e;
        w[j] = e;
        mx = fmaxf(mx, e);
    }
#pragma unroll
    for (int off = 16; off; off >>= 1)
        mx = fmaxf(mx, __shfl_xor_sync(0xffffffffu, mx, off));
    float sum = 0.f;
    for (int j = lo + lane; j < hi; j += 32) {
        float ex = __expf(w[j] - mx);
        w[j] = ex;
        sum += ex;
    }
#pragma unroll
    for (int off = 16; off; off >>= 1)
        sum += __shfl_xor_sync(0xffffffffu, sum, off);
    if (lane == 0) s[gw] = sum;
}

// ---------------- weighted gather-aggregate (one warp per dst node) ----------------
template <bool ELU>
__global__ void agg_kernel(const int* __restrict__ rowptr, const int* __restrict__ csrc,
                           const float* __restrict__ w, const float* __restrict__ s,
                           const float* __restrict__ h, const float* __restrict__ bias,
                           float* __restrict__ out, int n)
{
    int gw = (blockIdx.x * blockDim.x + threadIdx.x) >> 5;
    int lane = threadIdx.x & 31;
    if (gw >= n) return;
    int lo = rowptr[gw], hi = rowptr[gw + 1];
    const float4* __restrict__ h4 = (const float4*)h;
    float4 acc = make_float4(0.f, 0.f, 0.f, 0.f);
    for (int j = lo; j < hi; j++) {
        int srcn = __ldg(&csrc[j]);
        float wt = __ldg(&w[j]);
        float4 hv = __ldg(&h4[srcn * 32 + lane]);
        acc.x = fmaf(wt, hv.x, acc.x);
        acc.y = fmaf(wt, hv.y, acc.y);
        acc.z = fmaf(wt, hv.z, acc.z);
        acc.w = fmaf(wt, hv.w, acc.w);
    }
    float sv = s[gw];
    float inv = sv > 0.f ? 1.f / sv : 0.f;
    float4 b4 = ((const float4*)bias)[lane];
    float4 r;
    r.x = fmaf(acc.x, inv, b4.x);
    r.y = fmaf(acc.y, inv, b4.y);
    r.z = fmaf(acc.z, inv, b4.z);
    r.w = fmaf(acc.w, inv, b4.w);
    if (ELU) {
        r.x = r.x > 0.f ? r.x : __expf(r.x) - 1.f;
        r.y = r.y > 0.f ? r.y : __expf(r.y) - 1.f;
        r.z = r.z > 0.f ? r.z : __expf(r.z) - 1.f;
        r.w = r.w > 0.f ? r.w : __expf(r.w) - 1.f;
    }
    ((float4*)out)[gw * 32 + lane] = r;
}

// ---------------- launch ----------------
extern "C" void kernel_launch(void* const* d_in, const int* in_sizes, int n_in,
                              void* d_out, int out_size)
{
    const float* features = (const float*)d_in[0];
    const int*   src      = (const int*)d_in[1];
    const int*   dst      = (const int*)d_in[2];
    const float* W1       = (const float*)d_in[3];
    const float* al1      = (const float*)d_in[4];
    const float* ar1      = (const float*)d_in[5];
    const float* b1       = (const float*)d_in[6];
    const float* W2       = (const float*)d_in[7];
    const float* al2      = (const float*)d_in[8];
    const float* ar2      = (const float*)d_in[9];
    const float* b2       = (const float*)d_in[10];
    float* out = (float*)d_out;

    const int n = in_sizes[0] / IN_FEATS;   // 100000
    const int e = in_sizes[1];              // 1600000

    float *h, *x2, *el, *er, *sarr, *warr;
    int *rowptr, *cnt, *csrc;
    cudaGetSymbolAddress((void**)&h,      g_h);
    cudaGetSymbolAddress((void**)&x2,     g_x2);
    cudaGetSymbolAddress((void**)&el,     g_el);
    cudaGetSymbolAddress((void**)&er,     g_er);
    cudaGetSymbolAddress((void**)&sarr,   g_s);
    cudaGetSymbolAddress((void**)&warr,   g_w);
    cudaGetSymbolAddress((void**)&rowptr, g_rowptr);
    cudaGetSymbolAddress((void**)&cnt,    g_cnt);
    cudaGetSymbolAddress((void**)&csrc,   g_csrc);

    const int TPB = 256;
    const int eblocks = (e + TPB - 1) / TPB;
    const int nwarp_blocks = (n * 32 + TPB - 1) / TPB;
    const int tc_blocks = (n + 127) / 128;
    const int SMEM_TC = 1024 + 128 * 132 * 4 + 256;   // align pad + C-staging (> 64KB tiles)

    cudaFuncSetAttribute(gemm_mma<IN_FEATS>, cudaFuncAttributeMaxDynamicSharedMemorySize, SMEM_TC);
    cudaFuncSetAttribute(gemm_mma<HID>,      cudaFuncAttributeMaxDynamicSharedMemorySize, SMEM_TC);

    // CSR build (by dst)
    cudaMemsetAsync(cnt, 0, (size_t)(n + 1) * sizeof(int));
    hist_kernel<<<eblocks, TPB>>>(dst, cnt, e);
    scan_kernel<<<1, 1024>>>(cnt, rowptr, n);
    fill_kernel<<<eblocks, TPB>>>(src, dst, cnt, csrc, e);

    // ---- layer 1 ----
    gemm_mma<IN_FEATS><<<tc_blocks, TPB, SMEM_TC>>>(features, W1, al1, ar1, h, el, er, n);
    attn_kernel<<<nwarp_blocks, TPB>>>(rowptr, csrc, el, er, warr, sarr, n);
    agg_kernel<true><<<nwarp_blocks, TPB>>>(rowptr, csrc, warr, sarr, h, b1, x2, n);

    // ---- layer 2 ----
    gemm_mma<HID><<<tc_blocks, TPB, SMEM_TC>>>(x2, W2, al2, ar2, h, el, er, n);
    attn_kernel<<<nwarp_blocks, TPB>>>(rowptr, csrc, el, er, warr, sarr, n);
    agg_kernel<false><<<nwarp_blocks, TPB>>>(rowptr, csrc, warr, sarr, h, b2, out, n);
}

// round 9
// speedup vs baseline: 1.2565x; 1.0202x over previous
#include <cuda_runtime.h>
#include <cuda_bf16.h>
#include <math_constants.h>
#include <cstdint>

#define N_NODES 100000
#define N_EDGES 1600000
#define IN_FEATS 256
#define HID 128

typedef unsigned long long u64;

// ---------------- device scratch (static, allocation-free) ----------------
__device__ float g_h[N_NODES * HID];
__device__ float g_el[N_NODES];
__device__ float g_er[N_NODES];
__device__ int   g_rowptr[N_NODES + 1];
__device__ int   g_cnt[N_NODES + 1];
__device__ int   g_csrc[N_EDGES];
__device__ __nv_bfloat16 g_x2h[N_NODES * HID];
__device__ __nv_bfloat16 g_x2l[N_NODES * HID];
__device__ __nv_bfloat16 g_w1h[HID * IN_FEATS];
__device__ __nv_bfloat16 g_w1l[HID * IN_FEATS];
__device__ __nv_bfloat16 g_w2h[HID * HID];
__device__ __nv_bfloat16 g_w2l[HID * HID];

// ---------------- portable tensor-op helpers (sm_80+ PTX, valid on sm_103) ----
__device__ __forceinline__ uint32_t smem_u32(const void* p) {
    return (uint32_t)__cvta_generic_to_shared(p);
}
__device__ __forceinline__ void ldsm_x4(uint32_t* r, uint32_t addr) {
    asm volatile("ldmatrix.sync.aligned.m8n8.x4.shared.b16 {%0,%1,%2,%3}, [%4];"
                 : "=r"(r[0]), "=r"(r[1]), "=r"(r[2]), "=r"(r[3]) : "r"(addr));
}
__device__ __forceinline__ void ldsm_x2(uint32_t* r, uint32_t addr) {
    asm volatile("ldmatrix.sync.aligned.m8n8.x2.shared.b16 {%0,%1}, [%2];"
                 : "=r"(r[0]), "=r"(r[1]) : "r"(addr));
}
__device__ __forceinline__ void mma_bf16(float* d, const uint32_t* a, const uint32_t* b) {
    asm volatile(
        "mma.sync.aligned.m16n8k16.row.col.f32.bf16.bf16.f32 "
        "{%0,%1,%2,%3}, {%4,%5,%6,%7}, {%8,%9}, {%0,%1,%2,%3};"
        : "+f"(d[0]), "+f"(d[1]), "+f"(d[2]), "+f"(d[3])
        : "r"(a[0]), "r"(a[1]), "r"(a[2]), "r"(a[3]), "r"(b[0]), "r"(b[1]));
}
__device__ __forceinline__ uint32_t sw128(uint32_t off) {
    return off ^ ((off >> 3) & 0x70);
}
__device__ __forceinline__ void cp16(uint32_t dst, const void* src) {
    asm volatile("cp.async.ca.shared.global [%0], [%1], 16;" :: "r"(dst), "l"(src));
}
__device__ __forceinline__ void cp_commit() {
    asm volatile("cp.async.commit_group;" ::: "memory");
}
__device__ __forceinline__ void cp_wait0() {
    asm volatile("cp.async.wait_group 0;" ::: "memory");
}

// convert float4 -> bf16 hi/lo pairs and store (8B each) into swizzled tiles
__device__ __forceinline__ void stage_f4(char* tileH, char* tileL,
                                         int row, int k4, float4 v) {
    __nv_bfloat16 h0 = __float2bfloat16_rn(v.x);
    __nv_bfloat16 h1 = __float2bfloat16_rn(v.y);
    __nv_bfloat16 h2 = __float2bfloat16_rn(v.z);
    __nv_bfloat16 h3 = __float2bfloat16_rn(v.w);
    __nv_bfloat16 l0 = __float2bfloat16_rn(v.x - __bfloat162float(h0));
    __nv_bfloat16 l1 = __float2bfloat16_rn(v.y - __bfloat162float(h1));
    __nv_bfloat16 l2 = __float2bfloat16_rn(v.z - __bfloat162float(h2));
    __nv_bfloat16 l3 = __float2bfloat16_rn(v.w - __bfloat162float(h3));
    uint32_t hA = (uint32_t)__bfloat16_as_ushort(h0) | ((uint32_t)__bfloat16_as_ushort(h1) << 16);
    uint32_t hB = (uint32_t)__bfloat16_as_ushort(h2) | ((uint32_t)__bfloat16_as_ushort(h3) << 16);
    uint32_t lA = (uint32_t)__bfloat16_as_ushort(l0) | ((uint32_t)__bfloat16_as_ushort(l1) << 16);
    uint32_t lB = (uint32_t)__bfloat16_as_ushort(l2) | ((uint32_t)__bfloat16_as_ushort(l3) << 16);
    uint32_t sw = sw128((uint32_t)(row * 128 + k4 * 2));
    *(uint2*)(tileH + sw) = make_uint2(hA, hB);
    *(uint2*)(tileL + sw) = make_uint2(lA, lB);
}

// ---------------- one-time weight split: fp32 -> bf16 hi/lo ----------------
__global__ void split_kernel(const float* __restrict__ w,
                             __nv_bfloat16* __restrict__ wh,
                             __nv_bfloat16* __restrict__ wl, int total4) {
    int i = blockIdx.x * blockDim.x + threadIdx.x;
    if (i >= total4) return;
    float4 v = ((const float4*)w)[i];
    __nv_bfloat16 h0 = __float2bfloat16_rn(v.x);
    __nv_bfloat16 h1 = __float2bfloat16_rn(v.y);
    __nv_bfloat16 h2 = __float2bfloat16_rn(v.z);
    __nv_bfloat16 h3 = __float2bfloat16_rn(v.w);
    __nv_bfloat16 l0 = __float2bfloat16_rn(v.x - __bfloat162float(h0));
    __nv_bfloat16 l1 = __float2bfloat16_rn(v.y - __bfloat162float(h1));
    __nv_bfloat16 l2 = __float2bfloat16_rn(v.z - __bfloat162float(h2));
    __nv_bfloat16 l3 = __float2bfloat16_rn(v.w - __bfloat162float(h3));
    uint32_t hA = (uint32_t)__bfloat16_as_ushort(h0) | ((uint32_t)__bfloat16_as_ushort(h1) << 16);
    uint32_t hB = (uint32_t)__bfloat16_as_ushort(h2) | ((uint32_t)__bfloat16_as_ushort(h3) << 16);
    uint32_t lA = (uint32_t)__bfloat16_as_ushort(l0) | ((uint32_t)__bfloat16_as_ushort(l1) << 16);
    uint32_t lB = (uint32_t)__bfloat16_as_ushort(l2) | ((uint32_t)__bfloat16_as_ushort(l3) << 16);
    ((uint2*)wh)[i] = make_uint2(hA, hB);
    ((uint2*)wl)[i] = make_uint2(lA, lB);
}

// ---------------- CSR build ----------------
__global__ void hist_kernel(const int* __restrict__ dst, int* __restrict__ cnt, int e) {
    int i = blockIdx.x * blockDim.x + threadIdx.x;
    if (i < e) atomicAdd(&cnt[dst[i]], 1);
}

__global__ void scan_kernel(int* __restrict__ cnt, int* __restrict__ rowptr, int n) {
    __shared__ int ts[1024];
    int tid = threadIdx.x;
    int chunk = (n + 1023) / 1024;
    int lo = tid * chunk;
    int hi = lo + chunk; if (hi > n) hi = n; if (lo > n) lo = n;
    int sum = 0;
    for (int i = lo; i < hi; i++) sum += cnt[i];
    ts[tid] = sum;
    __syncthreads();
    for (int off = 1; off < 1024; off <<= 1) {
        int add = (tid >= off) ? ts[tid - off] : 0;
        __syncthreads();
        ts[tid] += add;
        __syncthreads();
    }
    int excl = ts[tid] - sum;
    int run = excl;
    for (int i = lo; i < hi; i++) {
        int c = cnt[i];
        rowptr[i] = run;
        cnt[i] = run;
        run += c;
    }
    if (tid == 1023) rowptr[n] = run;
}

__global__ void fill_kernel(const int* __restrict__ src, const int* __restrict__ dst,
                            int* __restrict__ cursor, int* __restrict__ csrc, int e) {
    int i = blockIdx.x * blockDim.x + threadIdx.x;
    if (i < e) {
        int d = dst[i];
        int p = atomicAdd(&cursor[d], 1);
        csrc[p] = src[i];
    }
}

// ---------------- mma.sync GEMM: H = X @ W^T (+ fused el/er epilogue) --------
// CTA tile: 128 nodes x 128 cols, 8 warps (4x2), warp tile m32 x n64.
// K-chunks of 64, SW128 smem. 3-pass bf16 split: D += Ah*Bh + Al*Bh + Ah*Bl.
// B always pre-split bf16 (cp.async). A: fp32+fused convert (PRESPLIT=false)
// or pre-split bf16 via cp.async (PRESPLIT=true).
template <int K, bool PRESPLIT>
__global__ void __launch_bounds__(256)
gemm_mma(const float* __restrict__ X,
         const __nv_bfloat16* __restrict__ XH, const __nv_bfloat16* __restrict__ XL,
         const __nv_bfloat16* __restrict__ WH, const __nv_bfloat16* __restrict__ WL,
         const float* __restrict__ al, const float* __restrict__ ar,
         float* __restrict__ H, float* __restrict__ el, float* __restrict__ er,
         int nnodes)
{
    extern __shared__ char smem_raw[];
    char* tiles = (char*)(((uintptr_t)smem_raw + 1023) & ~(uintptr_t)1023);
    char* tAH = tiles;
    char* tAL = tiles + 16384;
    char* tBH = tiles + 32768;
    char* tBL = tiles + 49152;
    const uint32_t aAH = smem_u32(tAH);
    const uint32_t aAL = smem_u32(tAL);
    const uint32_t aBH = smem_u32(tBH);
    const uint32_t aBL = smem_u32(tBL);

    const int tid  = threadIdx.x;
    const int lane = tid & 31;
    const int wid  = tid >> 5;
    const int node0 = blockIdx.x * 128;
    const int m0 = (wid >> 1) * 32;
    const int n0 = (wid & 1) * 64;

    const int arow = lane & 15;
    const uint32_t acol = ((lane >> 4) & 1) * 16;
    const int brow = lane & 7;
    const uint32_t bcol = ((lane >> 3) & 1) * 16;

    float d[2][8][4];
#pragma unroll
    for (int at = 0; at < 2; at++)
#pragma unroll
        for (int nt = 0; nt < 8; nt++)
#pragma unroll
            for (int i = 0; i < 4; i++) d[at][nt][i] = 0.f;

    constexpr int NCH = K / 64;

    float4 aregs[8];
    if (!PRESPLIT) {
        // prefetch A chunk 0 (fp32)
#pragma unroll
        for (int i = 0; i < 8; i++) {
            int gi = tid + i * 256;
            int row = gi >> 4;
            int k4 = (gi & 15) * 4;
            int node = node0 + row;
            if (node >= nnodes) node = nnodes - 1;
            aregs[i] = *(const float4*)(X + (size_t)node * K + k4);
        }
    }

#pragma unroll
    for (int c = 0; c < NCH; c++) {
        const int k0 = c * 64;
        if (PRESPLIT) {
            // A via cp.async: 2 tiles x 1024 16B-units, 8 units/thread
#pragma unroll
            for (int i = 0; i < 8; i++) {
                int gi = tid + i * 256;
                int t = gi >> 10;            // 0 = H, 1 = L
                int u = gi & 1023;
                int row = u >> 3;
                int uk = u & 7;
                int node = node0 + row;
                if (node >= nnodes) node = nnodes - 1;
                const __nv_bfloat16* srcb = (t ? XL : XH) + (size_t)node * K + k0 + uk * 8;
                uint32_t dstb = (t ? aAL : aAH) + sw128((uint32_t)(row * 128 + uk * 16));
                cp16(dstb, srcb);
            }
        } else {
            // stage prefetched A fp32 -> hi/lo bf16 smem
#pragma unroll
            for (int i = 0; i < 8; i++) {
                int gi = tid + i * 256;
                int row = gi >> 4;
                int k4 = (gi & 15) * 4;
                stage_f4(tAH, tAL, row, k4, aregs[i]);
            }
        }
        // B via cp.async (always pre-split)
#pragma unroll
        for (int i = 0; i < 8; i++) {
            int gi = tid + i * 256;
            int t = gi >> 10;
            int u = gi & 1023;
            int row = u >> 3;
            int uk = u & 7;
            const __nv_bfloat16* srcb = (t ? WL : WH) + (size_t)row * K + k0 + uk * 8;
            uint32_t dstb = (t ? aBL : aBH) + sw128((uint32_t)(row * 128 + uk * 16));
            cp16(dstb, srcb);
        }
        cp_commit();
        // prefetch next A chunk (fp32 path) while cp.async drains / MMA runs
        if (!PRESPLIT && c + 1 < NCH) {
#pragma unroll
            for (int i = 0; i < 8; i++) {
                int gi = tid + i * 256;
                int row = gi >> 4;
                int k4 = (gi & 15) * 4;
                int node = node0 + row;
                if (node >= nnodes) node = nnodes - 1;
                aregs[i] = *(const float4*)(X + (size_t)node * K + k0 + 64 + k4);
            }
        }
        cp_wait0();
        __syncthreads();

#pragma unroll
        for (int s = 0; s < 4; s++) {
            const uint32_t sb = (uint32_t)(s * 32);
            uint32_t ah[2][4], alo[2][4], bh[8][2], blo[8][2];
#pragma unroll
            for (int at = 0; at < 2; at++) {
                int row = m0 + at * 16 + arow;
                uint32_t sw = sw128((uint32_t)(row * 128) + sb + acol);
                ldsm_x4(ah[at],  aAH + sw);
                ldsm_x4(alo[at], aAL + sw);
            }
#pragma unroll
            for (int nt = 0; nt < 8; nt++) {
                int row = n0 + nt * 8 + brow;
                uint32_t sw = sw128((uint32_t)(row * 128) + sb + bcol);
                ldsm_x2(bh[nt],  aBH + sw);
                ldsm_x2(blo[nt], aBL + sw);
            }
#pragma unroll
            for (int at = 0; at < 2; at++)
#pragma unroll
                for (int nt = 0; nt < 8; nt++) {
                    mma_bf16(d[at][nt], ah[at],  bh[nt]);
                    mma_bf16(d[at][nt], alo[at], bh[nt]);
                    mma_bf16(d[at][nt], ah[at],  blo[nt]);
                }
        }
        __syncthreads();
    }

    // ---- epilogue: stage C to smem, coalesced writes + fused el/er ----
    float* cs = (float*)tiles;           // 128 x 132 fp32
#pragma unroll
    for (int at = 0; at < 2; at++) {
        int r0 = m0 + at * 16 + (lane >> 2);
#pragma unroll
        for (int nt = 0; nt < 8; nt++) {
            int cc = n0 + nt * 8 + (lane & 3) * 2;
            *(float2*)&cs[r0 * 132 + cc]       = make_float2(d[at][nt][0], d[at][nt][1]);
            *(float2*)&cs[(r0 + 8) * 132 + cc] = make_float2(d[at][nt][2], d[at][nt][3]);
        }
    }
    __syncthreads();
    {
        int row  = tid >> 1;
        int half = tid & 1;
        int node = node0 + row;
        bool valid = node < nnodes;
        float sl = 0.f, sr = 0.f;
        const float* crow = &cs[row * 132 + half * 64];
        if (valid) {
            float* hp = H + (size_t)node * HID + half * 64;
#pragma unroll
            for (int i = 0; i < 16; i++) {
                float4 v  = *(const float4*)(crow + 4 * i);
                float4 a4 = *(const float4*)(al + half * 64 + 4 * i);
                float4 r4 = *(const float4*)(ar + half * 64 + 4 * i);
                sl += v.x * a4.x + v.y * a4.y + v.z * a4.z + v.w * a4.w;
                sr += v.x * r4.x + v.y * r4.y + v.z * r4.z + v.w * r4.w;
                *(float4*)(hp + 4 * i) = v;
            }
        }
        sl += __shfl_xor_sync(0xffffffffu, sl, 1);
        sr += __shfl_xor_sync(0xffffffffu, sr, 1);
        if (valid && half == 0) { el[node] = sl; er[node] = sr; }
    }
}

// ---------------- merged softmax + aggregate (one warp per dst node) ---------
// Per-warp smem cache of edge exp-weights (deg <= 256; guarded fallback beyond).
// out = (sum_j ex_j * h[src_j]) / (sum_j ex_j) + bias [, elu]
template <bool ELU, bool SPLIT>
__global__ void __launch_bounds__(256)
attn_agg(const int* __restrict__ rowptr, const int* __restrict__ csrc,
         const float* __restrict__ el, const float* __restrict__ er,
         const float* __restrict__ h, const float* __restrict__ bias,
         float* __restrict__ outF,
         __nv_bfloat16* __restrict__ outH, __nv_bfloat16* __restrict__ outL, int n)
{
    __shared__ float es[8][257];
    const int w = threadIdx.x >> 5;
    const int lane = threadIdx.x & 31;
    const int gw = (blockIdx.x * blockDim.x + threadIdx.x) >> 5;
    if (gw >= n) return;
    const int lo = rowptr[gw], hi = rowptr[gw + 1];
    const int deg = hi - lo;
    const int cap = deg < 256 ? deg : 256;
    const float erd = er[gw];

    // pass 1: edge scores (leaky-relu) + max; cache scores in smem
    float mx = -CUDART_INF_F;
    for (int idx = lane; idx < cap; idx += 32) {
        float e = __ldg(&el[__ldg(&csrc[lo + idx])]) + erd;
        e = e > 0.f ? e : 0.2f * e;
        es[w][idx] = e;
        mx = fmaxf(mx, e);
    }
    for (int idx = 256 + lane; idx < deg; idx += 32) {     // rare overflow tail
        float e = __ldg(&el[__ldg(&csrc[lo + idx])]) + erd;
        e = e > 0.f ? e : 0.2f * e;
        mx = fmaxf(mx, e);
    }
#pragma unroll
    for (int off = 16; off; off >>= 1)
        mx = fmaxf(mx, __shfl_xor_sync(0xffffffffu, mx, off));
    __syncwarp();

    // pass 1.5: exponentiate cached scores in-place + partial sum
    float psum = 0.f;
    for (int idx = lane; idx < cap; idx += 32) {
        float ex = __expf(es[w][idx] - mx);
        es[w][idx] = ex;
        psum += ex;
    }
#pragma unroll
    for (int off = 16; off; off >>= 1)
        psum += __shfl_xor_sync(0xffffffffu, psum, off);
    __syncwarp();

    // pass 2: weighted gather-accumulate (warp-wide per edge, lane = 4 feats)
    const float4* __restrict__ h4 = (const float4*)h;
    float4 acc0 = make_float4(0.f, 0.f, 0.f, 0.f);
    float4 acc1 = make_float4(0.f, 0.f, 0.f, 0.f);
    int j = 0;
    for (; j + 1 < cap; j += 2) {
        float ex0 = es[w][j];
        float ex1 = es[w][j + 1];
        int s0 = __ldg(&csrc[lo + j]);
        int s1 = __ldg(&csrc[lo + j + 1]);
        float4 h0 = __ldg(&h4[s0 * 32 + lane]);
        float4 h1 = __ldg(&h4[s1 * 32 + lane]);
        acc0.x = fmaf(ex0, h0.x, acc0.x);
        acc0.y = fmaf(ex0, h0.y, acc0.y);
        acc0.z = fmaf(ex0, h0.z, acc0.z);
        acc0.w = fmaf(ex0, h0.w, acc0.w);
        acc1.x = fmaf(ex1, h1.x, acc1.x);
        acc1.y = fmaf(ex1, h1.y, acc1.y);
        acc1.z = fmaf(ex1, h1.z, acc1.z);
        acc1.w = fmaf(ex1, h1.w, acc1.w);
    }
    if (j < cap) {
        float ex0 = es[w][j];
        int s0 = __ldg(&csrc[lo + j]);
        float4 h0 = __ldg(&h4[s0 * 32 + lane]);
        acc0.x = fmaf(ex0, h0.x, acc0.x);
        acc0.y = fmaf(ex0, h0.y, acc0.y);
        acc0.z = fmaf(ex0, h0.z, acc0.z);
        acc0.w = fmaf(ex0, h0.w, acc0.w);
    }
    float tsum = 0.f;                                       // rare overflow tail
    for (int jj = 256; jj < deg; jj++) {
        int s0 = __ldg(&csrc[lo + jj]);
        float e = __ldg(&el[s0]) + erd;
        e = e > 0.f ? e : 0.2f * e;
        float ex = __expf(e - mx);                          // warp-uniform
        tsum += ex;
        float4 h0 = __ldg(&h4[s0 * 32 + lane]);
        acc0.x = fmaf(ex, h0.x, acc0.x);
        acc0.y = fmaf(ex, h0.y, acc0.y);
        acc0.z = fmaf(ex, h0.z, acc0.z);
        acc0.w = fmaf(ex, h0.w, acc0.w);
    }

    float sum = psum + tsum;
    float inv = sum > 0.f ? 1.f / sum : 0.f;
    float4 acc = make_float4(acc0.x + acc1.x, acc0.y + acc1.y,
                             acc0.z + acc1.z, acc0.w + acc1.w);
    float4 b4 = ((const float4*)bias)[lane];
    float4 r;
    r.x = fmaf(acc.x, inv, b4.x);
    r.y = fmaf(acc.y, inv, b4.y);
    r.z = fmaf(acc.z, inv, b4.z);
    r.w = fmaf(acc.w, inv, b4.w);
    if (ELU) {
        r.x = r.x > 0.f ? r.x : __expf(r.x) - 1.f;
        r.y = r.y > 0.f ? r.y : __expf(r.y) - 1.f;
        r.z = r.z > 0.f ? r.z : __expf(r.z) - 1.f;
        r.w = r.w > 0.f ? r.w : __expf(r.w) - 1.f;
    }
    if (SPLIT) {
        __nv_bfloat16 h0 = __float2bfloat16_rn(r.x);
        __nv_bfloat16 h1 = __float2bfloat16_rn(r.y);
        __nv_bfloat16 h2 = __float2bfloat16_rn(r.z);
        __nv_bfloat16 h3 = __float2bfloat16_rn(r.w);
        __nv_bfloat16 l0 = __float2bfloat16_rn(r.x - __bfloat162float(h0));
        __nv_bfloat16 l1 = __float2bfloat16_rn(r.y - __bfloat162float(h1));
        __nv_bfloat16 l2 = __float2bfloat16_rn(r.z - __bfloat162float(h2));
        __nv_bfloat16 l3 = __float2bfloat16_rn(r.w - __bfloat162float(h3));
        uint2 hv = make_uint2(
            (uint32_t)__bfloat16_as_ushort(h0) | ((uint32_t)__bfloat16_as_ushort(h1) << 16),
            (uint32_t)__bfloat16_as_ushort(h2) | ((uint32_t)__bfloat16_as_ushort(h3) << 16));
        uint2 lv = make_uint2(
            (uint32_t)__bfloat16_as_ushort(l0) | ((uint32_t)__bfloat16_as_ushort(l1) << 16),
            (uint32_t)__bfloat16_as_ushort(l2) | ((uint32_t)__bfloat16_as_ushort(l3) << 16));
        *(uint2*)&outH[(size_t)gw * HID + lane * 4] = hv;
        *(uint2*)&outL[(size_t)gw * HID + lane * 4] = lv;
    } else {
        ((float4*)outF)[gw * 32 + lane] = r;
    }
}

// ---------------- launch ----------------
extern "C" void kernel_launch(void* const* d_in, const int* in_sizes, int n_in,
                              void* d_out, int out_size)
{
    const float* features = (const float*)d_in[0];
    const int*   src      = (const int*)d_in[1];
    const int*   dst      = (const int*)d_in[2];
    const float* W1       = (const float*)d_in[3];
    const float* al1      = (const float*)d_in[4];
    const float* ar1      = (const float*)d_in[5];
    const float* b1       = (const float*)d_in[6];
    const float* W2       = (const float*)d_in[7];
    const float* al2      = (const float*)d_in[8];
    const float* ar2      = (const float*)d_in[9];
    const float* b2       = (const float*)d_in[10];
    float* out = (float*)d_out;

    const int n = in_sizes[0] / IN_FEATS;   // 100000
    const int e = in_sizes[1];              // 1600000

    float *h, *el, *er;
    int *rowptr, *cnt, *csrc;
    __nv_bfloat16 *x2h, *x2l, *w1h, *w1l, *w2h, *w2l;
    cudaGetSymbolAddress((void**)&h,      g_h);
    cudaGetSymbolAddress((void**)&el,     g_el);
    cudaGetSymbolAddress((void**)&er,     g_er);
    cudaGetSymbolAddress((void**)&rowptr, g_rowptr);
    cudaGetSymbolAddress((void**)&cnt,    g_cnt);
    cudaGetSymbolAddress((void**)&csrc,   g_csrc);
    cudaGetSymbolAddress((void**)&x2h,    g_x2h);
    cudaGetSymbolAddress((void**)&x2l,    g_x2l);
    cudaGetSymbolAddress((void**)&w1h,    g_w1h);
    cudaGetSymbolAddress((void**)&w1l,    g_w1l);
    cudaGetSymbolAddress((void**)&w2h,    g_w2h);
    cudaGetSymbolAddress((void**)&w2l,    g_w2l);

    const int TPB = 256;
    const int eblocks = (e + TPB - 1) / TPB;
    const int nwarp_blocks = (n * 32 + TPB - 1) / TPB;
    const int tc_blocks = (n + 127) / 128;
    const int SMEM_TC = 1024 + 128 * 132 * 4 + 256;

    cudaFuncSetAttribute((const void*)gemm_mma<IN_FEATS, false>,
                         cudaFuncAttributeMaxDynamicSharedMemorySize, SMEM_TC);
    cudaFuncSetAttribute((const void*)gemm_mma<HID, true>,
                         cudaFuncAttributeMaxDynamicSharedMemorySize, SMEM_TC);

    // weight pre-split (once per call, tiny)
    split_kernel<<<(HID * IN_FEATS / 4 + 255) / 256, 256>>>(W1, w1h, w1l, HID * IN_FEATS / 4);
    split_kernel<<<(HID * HID / 4 + 255) / 256, 256>>>(W2, w2h, w2l, HID * HID / 4);

    // CSR build (by dst)
    cudaMemsetAsync(cnt, 0, (size_t)(n + 1) * sizeof(int));
    hist_kernel<<<eblocks, TPB>>>(dst, cnt, e);
    scan_kernel<<<1, 1024>>>(cnt, rowptr, n);
    fill_kernel<<<eblocks, TPB>>>(src, dst, cnt, csrc, e);

    // ---- layer 1 ----
    gemm_mma<IN_FEATS, false><<<tc_blocks, TPB, SMEM_TC>>>(
        features, nullptr, nullptr, w1h, w1l, al1, ar1, h, el, er, n);
    attn_agg<true, true><<<nwarp_blocks, TPB>>>(
        rowptr, csrc, el, er, h, b1, nullptr, x2h, x2l, n);

    // ---- layer 2 ----
    gemm_mma<HID, true><<<tc_blocks, TPB, SMEM_TC>>>(
        nullptr, x2h, x2l, w2h, w2l, al2, ar2, h, el, er, n);
    attn_agg<false, false><<<nwarp_blocks, TPB>>>(
        rowptr, csrc, el, er, h, b2, out, nullptr, nullptr, n);
}

// round 10
// speedup vs baseline: 1.7179x; 1.3672x over previous
#include <cuda_runtime.h>
#include <cuda_bf16.h>
#include <math_constants.h>
#include <cstdint>

#define N_NODES 100000
#define N_EDGES 1600000
#define IN_FEATS 256
#define HID 128

typedef unsigned long long u64;

// ---------------- device scratch (static, allocation-free) ----------------
__device__ float g_h[N_NODES * HID];
__device__ float g_el[N_NODES];
__device__ float g_er[N_NODES];
__device__ int   g_rowptr[N_NODES + 1];
__device__ int   g_cnt[N_NODES + 1];
__device__ int   g_csrc[N_EDGES];
__device__ int   g_bsum[256];
__device__ __nv_bfloat16 g_x2h[N_NODES * HID];
__device__ __nv_bfloat16 g_x2l[N_NODES * HID];
__device__ __nv_bfloat16 g_w1h[HID * IN_FEATS];
__device__ __nv_bfloat16 g_w1l[HID * IN_FEATS];
__device__ __nv_bfloat16 g_w2h[HID * HID];
__device__ __nv_bfloat16 g_w2l[HID * HID];

// ---------------- portable tensor-op helpers (sm_80+ PTX, valid on sm_103) ----
__device__ __forceinline__ uint32_t smem_u32(const void* p) {
    return (uint32_t)__cvta_generic_to_shared(p);
}
__device__ __forceinline__ void ldsm_x4(uint32_t* r, uint32_t addr) {
    asm volatile("ldmatrix.sync.aligned.m8n8.x4.shared.b16 {%0,%1,%2,%3}, [%4];"
                 : "=r"(r[0]), "=r"(r[1]), "=r"(r[2]), "=r"(r[3]) : "r"(addr));
}
__device__ __forceinline__ void ldsm_x2(uint32_t* r, uint32_t addr) {
    asm volatile("ldmatrix.sync.aligned.m8n8.x2.shared.b16 {%0,%1}, [%2];"
                 : "=r"(r[0]), "=r"(r[1]) : "r"(addr));
}
__device__ __forceinline__ void mma_bf16(float* d, const uint32_t* a, const uint32_t* b) {
    asm volatile(
        "mma.sync.aligned.m16n8k16.row.col.f32.bf16.bf16.f32 "
        "{%0,%1,%2,%3}, {%4,%5,%6,%7}, {%8,%9}, {%0,%1,%2,%3};"
        : "+f"(d[0]), "+f"(d[1]), "+f"(d[2]), "+f"(d[3])
        : "r"(a[0]), "r"(a[1]), "r"(a[2]), "r"(a[3]), "r"(b[0]), "r"(b[1]));
}
__device__ __forceinline__ uint32_t sw128(uint32_t off) {
    return off ^ ((off >> 3) & 0x70);
}
__device__ __forceinline__ void cp16(uint32_t dst, const void* src) {
    asm volatile("cp.async.ca.shared.global [%0], [%1], 16;" :: "r"(dst), "l"(src));
}
__device__ __forceinline__ void cp_commit() {
    asm volatile("cp.async.commit_group;" ::: "memory");
}
__device__ __forceinline__ void cp_wait0() {
    asm volatile("cp.async.wait_group 0;" ::: "memory");
}

// convert float4 -> bf16 hi/lo pairs and store (8B each) into swizzled tiles
__device__ __forceinline__ void stage_f4(char* tileH, char* tileL,
                                         int row, int k4, float4 v) {
    __nv_bfloat16 h0 = __float2bfloat16_rn(v.x);
    __nv_bfloat16 h1 = __float2bfloat16_rn(v.y);
    __nv_bfloat16 h2 = __float2bfloat16_rn(v.z);
    __nv_bfloat16 h3 = __float2bfloat16_rn(v.w);
    __nv_bfloat16 l0 = __float2bfloat16_rn(v.x - __bfloat162float(h0));
    __nv_bfloat16 l1 = __float2bfloat16_rn(v.y - __bfloat162float(h1));
    __nv_bfloat16 l2 = __float2bfloat16_rn(v.z - __bfloat162float(h2));
    __nv_bfloat16 l3 = __float2bfloat16_rn(v.w - __bfloat162float(h3));
    uint32_t hA = (uint32_t)__bfloat16_as_ushort(h0) | ((uint32_t)__bfloat16_as_ushort(h1) << 16);
    uint32_t hB = (uint32_t)__bfloat16_as_ushort(h2) | ((uint32_t)__bfloat16_as_ushort(h3) << 16);
    uint32_t lA = (uint32_t)__bfloat16_as_ushort(l0) | ((uint32_t)__bfloat16_as_ushort(l1) << 16);
    uint32_t lB = (uint32_t)__bfloat16_as_ushort(l2) | ((uint32_t)__bfloat16_as_ushort(l3) << 16);
    uint32_t sw = sw128((uint32_t)(row * 128 + k4 * 2));
    *(uint2*)(tileH + sw) = make_uint2(hA, hB);
    *(uint2*)(tileL + sw) = make_uint2(lA, lB);
}

// ---------------- one-time weight split: fp32 -> bf16 hi/lo ----------------
__global__ void split_kernel(const float* __restrict__ w,
                             __nv_bfloat16* __restrict__ wh,
                             __nv_bfloat16* __restrict__ wl, int total4) {
    int i = blockIdx.x * blockDim.x + threadIdx.x;
    if (i >= total4) return;
    float4 v = ((const float4*)w)[i];
    __nv_bfloat16 h0 = __float2bfloat16_rn(v.x);
    __nv_bfloat16 h1 = __float2bfloat16_rn(v.y);
    __nv_bfloat16 h2 = __float2bfloat16_rn(v.z);
    __nv_bfloat16 h3 = __float2bfloat16_rn(v.w);
    __nv_bfloat16 l0 = __float2bfloat16_rn(v.x - __bfloat162float(h0));
    __nv_bfloat16 l1 = __float2bfloat16_rn(v.y - __bfloat162float(h1));
    __nv_bfloat16 l2 = __float2bfloat16_rn(v.z - __bfloat162float(h2));
    __nv_bfloat16 l3 = __float2bfloat16_rn(v.w - __bfloat162float(h3));
    uint32_t hA = (uint32_t)__bfloat16_as_ushort(h0) | ((uint32_t)__bfloat16_as_ushort(h1) << 16);
    uint32_t hB = (uint32_t)__bfloat16_as_ushort(h2) | ((uint32_t)__bfloat16_as_ushort(h3) << 16);
    uint32_t lA = (uint32_t)__bfloat16_as_ushort(l0) | ((uint32_t)__bfloat16_as_ushort(l1) << 16);
    uint32_t lB = (uint32_t)__bfloat16_as_ushort(l2) | ((uint32_t)__bfloat16_as_ushort(l3) << 16);
    ((uint2*)wh)[i] = make_uint2(hA, hB);
    ((uint2*)wl)[i] = make_uint2(lA, lB);
}

// ---------------- CSR build ----------------
__global__ void hist_kernel(const int* __restrict__ dst, int* __restrict__ cnt, int e) {
    int i = blockIdx.x * blockDim.x + threadIdx.x;
    if (i < e) atomicAdd(&cnt[dst[i]], 1);
}

// ---- 3-phase decoupled exclusive scan of cnt[0..n) -> rowptr / cursor ----
#define SCAN_B 1024

__global__ void blocksum_kernel(const int* __restrict__ cnt, int* __restrict__ bsum, int n) {
    __shared__ int ws[32];
    int i = blockIdx.x * SCAN_B + threadIdx.x;
    int v = (i < n) ? cnt[i] : 0;
#pragma unroll
    for (int off = 16; off; off >>= 1)
        v += __shfl_xor_sync(0xffffffffu, v, off);
    if ((threadIdx.x & 31) == 0) ws[threadIdx.x >> 5] = v;
    __syncthreads();
    if (threadIdx.x < 32) {
        int s = ws[threadIdx.x];
#pragma unroll
        for (int off = 16; off; off >>= 1)
            s += __shfl_xor_sync(0xffffffffu, s, off);
        if (threadIdx.x == 0) bsum[blockIdx.x] = s;
    }
}

__global__ void scan_partials_kernel(int* __restrict__ bsum, int nb) {
    // single block, <=256 partials: simple smem Hillis-Steele
    __shared__ int ts[256];
    int tid = threadIdx.x;
    int v = (tid < nb) ? bsum[tid] : 0;
    ts[tid] = v;
    __syncthreads();
    for (int off = 1; off < 256; off <<= 1) {
        int add = (tid >= off) ? ts[tid - off] : 0;
        __syncthreads();
        ts[tid] += add;
        __syncthreads();
    }
    if (tid < nb) bsum[tid] = ts[tid] - v;   // exclusive
}

__global__ void scan_apply_kernel(int* __restrict__ cnt, const int* __restrict__ bsum,
                                  int* __restrict__ rowptr, int n) {
    __shared__ int ws[32];
    const int tid = threadIdx.x;
    const int lane = tid & 31;
    const int warp = tid >> 5;
    int i = blockIdx.x * SCAN_B + tid;
    int x = (i < n) ? cnt[i] : 0;
    // warp inclusive scan
    int inc = x;
#pragma unroll
    for (int off = 1; off < 32; off <<= 1) {
        int t = __shfl_up_sync(0xffffffffu, inc, off);
        if (lane >= off) inc += t;
    }
    if (lane == 31) ws[warp] = inc;
    __syncthreads();
    if (warp == 0) {
        int s = (lane < 32) ? ws[lane] : 0;
#pragma unroll
        for (int off = 1; off < 32; off <<= 1) {
            int t = __shfl_up_sync(0xffffffffu, s, off);
            if (lane >= off) s += t;
        }
        ws[lane] = s;
    }
    __syncthreads();
    int excl = inc - x + (warp ? ws[warp - 1] : 0) + bsum[blockIdx.x];
    if (i < n) {
        rowptr[i] = excl;
        cnt[i] = excl;                        // cursor
        if (i == n - 1) rowptr[n] = excl + x; // total
    }
}

__global__ void fill_kernel(const int* __restrict__ src, const int* __restrict__ dst,
                            int* __restrict__ cursor, int* __restrict__ csrc, int e) {
    int i = blockIdx.x * blockDim.x + threadIdx.x;
    if (i < e) {
        int d = dst[i];
        int p = atomicAdd(&cursor[d], 1);
        csrc[p] = src[i];
    }
}

// ---------------- mma.sync GEMM: H = X @ W^T (+ fused el/er epilogue) --------
// CTA tile: 128 nodes x 128 cols, 8 warps (4x2), warp tile m32 x n64.
// K-chunks of 64, SW128 smem. 3-pass bf16 split: D += Ah*Bh + Al*Bh + Ah*Bl.
template <int K, bool PRESPLIT>
__global__ void __launch_bounds__(256)
gemm_mma(const float* __restrict__ X,
         const __nv_bfloat16* __restrict__ XH, const __nv_bfloat16* __restrict__ XL,
         const __nv_bfloat16* __restrict__ WH, const __nv_bfloat16* __restrict__ WL,
         const float* __restrict__ al, const float* __restrict__ ar,
         float* __restrict__ H, float* __restrict__ el, float* __restrict__ er,
         int nnodes)
{
    extern __shared__ char smem_raw[];
    char* tiles = (char*)(((uintptr_t)smem_raw + 1023) & ~(uintptr_t)1023);
    char* tAH = tiles;
    char* tAL = tiles + 16384;
    char* tBH = tiles + 32768;
    char* tBL = tiles + 49152;
    const uint32_t aAH = smem_u32(tAH);
    const uint32_t aAL = smem_u32(tAL);
    const uint32_t aBH = smem_u32(tBH);
    const uint32_t aBL = smem_u32(tBL);

    const int tid  = threadIdx.x;
    const int lane = tid & 31;
    const int wid  = tid >> 5;
    const int node0 = blockIdx.x * 128;
    const int m0 = (wid >> 1) * 32;
    const int n0 = (wid & 1) * 64;

    const int arow = lane & 15;
    const uint32_t acol = ((lane >> 4) & 1) * 16;
    const int brow = lane & 7;
    const uint32_t bcol = ((lane >> 3) & 1) * 16;

    float d[2][8][4];
#pragma unroll
    for (int at = 0; at < 2; at++)
#pragma unroll
        for (int nt = 0; nt < 8; nt++)
#pragma unroll
            for (int i = 0; i < 4; i++) d[at][nt][i] = 0.f;

    constexpr int NCH = K / 64;

    float4 aregs[8];
    if (!PRESPLIT) {
#pragma unroll
        for (int i = 0; i < 8; i++) {
            int gi = tid + i * 256;
            int row = gi >> 4;
            int k4 = (gi & 15) * 4;
            int node = node0 + row;
            if (node >= nnodes) node = nnodes - 1;
            aregs[i] = *(const float4*)(X + (size_t)node * K + k4);
        }
    }

#pragma unroll
    for (int c = 0; c < NCH; c++) {
        const int k0 = c * 64;
        if (PRESPLIT) {
#pragma unroll
            for (int i = 0; i < 8; i++) {
                int gi = tid + i * 256;
                int t = gi >> 10;            // 0 = H, 1 = L
                int u = gi & 1023;
                int row = u >> 3;
                int uk = u & 7;
                int node = node0 + row;
                if (node >= nnodes) node = nnodes - 1;
                const __nv_bfloat16* srcb = (t ? XL : XH) + (size_t)node * K + k0 + uk * 8;
                uint32_t dstb = (t ? aAL : aAH) + sw128((uint32_t)(row * 128 + uk * 16));
                cp16(dstb, srcb);
            }
        } else {
#pragma unroll
            for (int i = 0; i < 8; i++) {
                int gi = tid + i * 256;
                int row = gi >> 4;
                int k4 = (gi & 15) * 4;
                stage_f4(tAH, tAL, row, k4, aregs[i]);
            }
        }
        // B via cp.async (always pre-split)
#pragma unroll
        for (int i = 0; i < 8; i++) {
            int gi = tid + i * 256;
            int t = gi >> 10;
            int u = gi & 1023;
            int row = u >> 3;
            int uk = u & 7;
            const __nv_bfloat16* srcb = (t ? WL : WH) + (size_t)row * K + k0 + uk * 8;
            uint32_t dstb = (t ? aBL : aBH) + sw128((uint32_t)(row * 128 + uk * 16));
            cp16(dstb, srcb);
        }
        cp_commit();
        if (!PRESPLIT && c + 1 < NCH) {
#pragma unroll
            for (int i = 0; i < 8; i++) {
                int gi = tid + i * 256;
                int row = gi >> 4;
                int k4 = (gi & 15) * 4;
                int node = node0 + row;
                if (node >= nnodes) node = nnodes - 1;
                aregs[i] = *(const float4*)(X + (size_t)node * K + k0 + 64 + k4);
            }
        }
        cp_wait0();
        __syncthreads();

#pragma unroll
        for (int s = 0; s < 4; s++) {
            const uint32_t sb = (uint32_t)(s * 32);
            uint32_t ah[2][4], alo[2][4], bh[8][2], blo[8][2];
#pragma unroll
            for (int at = 0; at < 2; at++) {
                int row = m0 + at * 16 + arow;
                uint32_t sw = sw128((uint32_t)(row * 128) + sb + acol);
                ldsm_x4(ah[at],  aAH + sw);
                ldsm_x4(alo[at], aAL + sw);
            }
#pragma unroll
            for (int nt = 0; nt < 8; nt++) {
                int row = n0 + nt * 8 + brow;
                uint32_t sw = sw128((uint32_t)(row * 128) + sb + bcol);
                ldsm_x2(bh[nt],  aBH + sw);
                ldsm_x2(blo[nt], aBL + sw);
            }
#pragma unroll
            for (int at = 0; at < 2; at++)
#pragma unroll
                for (int nt = 0; nt < 8; nt++) {
                    mma_bf16(d[at][nt], ah[at],  bh[nt]);
                    mma_bf16(d[at][nt], alo[at], bh[nt]);
                    mma_bf16(d[at][nt], ah[at],  blo[nt]);
                }
        }
        __syncthreads();
    }

    // ---- epilogue: stage C to smem, coalesced writes + fused el/er ----
    float* cs = (float*)tiles;           // 128 x 132 fp32
#pragma unroll
    for (int at = 0; at < 2; at++) {
        int r0 = m0 + at * 16 + (lane >> 2);
#pragma unroll
        for (int nt = 0; nt < 8; nt++) {
            int cc = n0 + nt * 8 + (lane & 3) * 2;
            *(float2*)&cs[r0 * 132 + cc]       = make_float2(d[at][nt][0], d[at][nt][1]);
            *(float2*)&cs[(r0 + 8) * 132 + cc] = make_float2(d[at][nt][2], d[at][nt][3]);
        }
    }
    __syncthreads();
    {
        int row  = tid >> 1;
        int half = tid & 1;
        int node = node0 + row;
        bool valid = node < nnodes;
        float sl = 0.f, sr = 0.f;
        const float* crow = &cs[row * 132 + half * 64];
        if (valid) {
            float* hp = H + (size_t)node * HID + half * 64;
#pragma unroll
            for (int i = 0; i < 16; i++) {
                float4 v  = *(const float4*)(crow + 4 * i);
                float4 a4 = *(const float4*)(al + half * 64 + 4 * i);
                float4 r4 = *(const float4*)(ar + half * 64 + 4 * i);
                sl += v.x * a4.x + v.y * a4.y + v.z * a4.z + v.w * a4.w;
                sr += v.x * r4.x + v.y * r4.y + v.z * r4.z + v.w * r4.w;
                *(float4*)(hp + 4 * i) = v;
            }
        }
        sl += __shfl_xor_sync(0xffffffffu, sl, 1);
        sr += __shfl_xor_sync(0xffffffffu, sr, 1);
        if (valid && half == 0) { el[node] = sl; er[node] = sr; }
    }
}

// ---------------- merged softmax + aggregate (one warp per dst node) ---------
template <bool ELU, bool SPLIT>
__global__ void __launch_bounds__(256)
attn_agg(const int* __restrict__ rowptr, const int* __restrict__ csrc,
         const float* __restrict__ el, const float* __restrict__ er,
         const float* __restrict__ h, const float* __restrict__ bias,
         float* __restrict__ outF,
         __nv_bfloat16* __restrict__ outH, __nv_bfloat16* __restrict__ outL, int n)
{
    __shared__ float es[8][257];
    const int w = threadIdx.x >> 5;
    const int lane = threadIdx.x & 31;
    const int gw = (blockIdx.x * blockDim.x + threadIdx.x) >> 5;
    if (gw >= n) return;
    const int lo = rowptr[gw], hi = rowptr[gw + 1];
    const int deg = hi - lo;
    const int cap = deg < 256 ? deg : 256;
    const float erd = er[gw];

    float mx = -CUDART_INF_F;
    for (int idx = lane; idx < cap; idx += 32) {
        float e = __ldg(&el[__ldg(&csrc[lo + idx])]) + erd;
        e = e > 0.f ? e : 0.2f * e;
        es[w][idx] = e;
        mx = fmaxf(mx, e);
    }
    for (int idx = 256 + lane; idx < deg; idx += 32) {
        float e = __ldg(&el[__ldg(&csrc[lo + idx])]) + erd;
        e = e > 0.f ? e : 0.2f * e;
        mx = fmaxf(mx, e);
    }
#pragma unroll
    for (int off = 16; off; off >>= 1)
        mx = fmaxf(mx, __shfl_xor_sync(0xffffffffu, mx, off));
    __syncwarp();

    float psum = 0.f;
    for (int idx = lane; idx < cap; idx += 32) {
        float ex = __expf(es[w][idx] - mx);
        es[w][idx] = ex;
        psum += ex;
    }
#pragma unroll
    for (int off = 16; off; off >>= 1)
        psum += __shfl_xor_sync(0xffffffffu, psum, off);
    __syncwarp();

    const float4* __restrict__ h4 = (const float4*)h;
    float4 acc0 = make_float4(0.f, 0.f, 0.f, 0.f);
    float4 acc1 = make_float4(0.f, 0.f, 0.f, 0.f);
    int j = 0;
    for (; j + 1 < cap; j += 2) {
        float ex0 = es[w][j];
        float ex1 = es[w][j + 1];
        int s0 = __ldg(&csrc[lo + j]);
        int s1 = __ldg(&csrc[lo + j + 1]);
        float4 h0 = __ldg(&h4[s0 * 32 + lane]);
        float4 h1 = __ldg(&h4[s1 * 32 + lane]);
        acc0.x = fmaf(ex0, h0.x, acc0.x);
        acc0.y = fmaf(ex0, h0.y, acc0.y);
        acc0.z = fmaf(ex0, h0.z, acc0.z);
        acc0.w = fmaf(ex0, h0.w, acc0.w);
        acc1.x = fmaf(ex1, h1.x, acc1.x);
        acc1.y = fmaf(ex1, h1.y, acc1.y);
        acc1.z = fmaf(ex1, h1.z, acc1.z);
        acc1.w = fmaf(ex1, h1.w, acc1.w);
    }
    if (j < cap) {
        float ex0 = es[w][j];
        int s0 = __ldg(&csrc[lo + j]);
        float4 h0 = __ldg(&h4[s0 * 32 + lane]);
        acc0.x = fmaf(ex0, h0.x, acc0.x);
        acc0.y = fmaf(ex0, h0.y, acc0.y);
        acc0.z = fmaf(ex0, h0.z, acc0.z);
        acc0.w = fmaf(ex0, h0.w, acc0.w);
    }
    float tsum = 0.f;
    for (int jj = 256; jj < deg; jj++) {
        int s0 = __ldg(&csrc[lo + jj]);
        float e = __ldg(&el[s0]) + erd;
        e = e > 0.f ? e : 0.2f * e;
        float ex = __expf(e - mx);
        tsum += ex;
        float4 h0 = __ldg(&h4[s0 * 32 + lane]);
        acc0.x = fmaf(ex, h0.x, acc0.x);
        acc0.y = fmaf(ex, h0.y, acc0.y);
        acc0.z = fmaf(ex, h0.z, acc0.z);
        acc0.w = fmaf(ex, h0.w, acc0.w);
    }

    float sum = psum + tsum;
    float inv = sum > 0.f ? 1.f / sum : 0.f;
    float4 acc = make_float4(acc0.x + acc1.x, acc0.y + acc1.y,
                             acc0.z + acc1.z, acc0.w + acc1.w);
    float4 b4 = ((const float4*)bias)[lane];
    float4 r;
    r.x = fmaf(acc.x, inv, b4.x);
    r.y = fmaf(acc.y, inv, b4.y);
    r.z = fmaf(acc.z, inv, b4.z);
    r.w = fmaf(acc.w, inv, b4.w);
    if (ELU) {
        r.x = r.x > 0.f ? r.x : __expf(r.x) - 1.f;
        r.y = r.y > 0.f ? r.y : __expf(r.y) - 1.f;
        r.z = r.z > 0.f ? r.z : __expf(r.z) - 1.f;
        r.w = r.w > 0.f ? r.w : __expf(r.w) - 1.f;
    }
    if (SPLIT) {
        __nv_bfloat16 h0 = __float2bfloat16_rn(r.x);
        __nv_bfloat16 h1 = __float2bfloat16_rn(r.y);
        __nv_bfloat16 h2 = __float2bfloat16_rn(r.z);
        __nv_bfloat16 h3 = __float2bfloat16_rn(r.w);
        __nv_bfloat16 l0 = __float2bfloat16_rn(r.x - __bfloat162float(h0));
        __nv_bfloat16 l1 = __float2bfloat16_rn(r.y - __bfloat162float(h1));
        __nv_bfloat16 l2 = __float2bfloat16_rn(r.z - __bfloat162float(h2));
        __nv_bfloat16 l3 = __float2bfloat16_rn(r.w - __bfloat162float(h3));
        uint2 hv = make_uint2(
            (uint32_t)__bfloat16_as_ushort(h0) | ((uint32_t)__bfloat16_as_ushort(h1) << 16),
            (uint32_t)__bfloat16_as_ushort(h2) | ((uint32_t)__bfloat16_as_ushort(h3) << 16));
        uint2 lv = make_uint2(
            (uint32_t)__bfloat16_as_ushort(l0) | ((uint32_t)__bfloat16_as_ushort(l1) << 16),
            (uint32_t)__bfloat16_as_ushort(l2) | ((uint32_t)__bfloat16_as_ushort(l3) << 16));
        *(uint2*)&outH[(size_t)gw * HID + lane * 4] = hv;
        *(uint2*)&outL[(size_t)gw * HID + lane * 4] = lv;
    } else {
        ((float4*)outF)[gw * 32 + lane] = r;
    }
}

// ---------------- launch ----------------
extern "C" void kernel_launch(void* const* d_in, const int* in_sizes, int n_in,
                              void* d_out, int out_size)
{
    const float* features = (const float*)d_in[0];
    const int*   src      = (const int*)d_in[1];
    const int*   dst      = (const int*)d_in[2];
    const float* W1       = (const float*)d_in[3];
    const float* al1      = (const float*)d_in[4];
    const float* ar1      = (const float*)d_in[5];
    const float* b1       = (const float*)d_in[6];
    const float* W2       = (const float*)d_in[7];
    const float* al2      = (const float*)d_in[8];
    const float* ar2      = (const float*)d_in[9];
    const float* b2       = (const float*)d_in[10];
    float* out = (float*)d_out;

    const int n = in_sizes[0] / IN_FEATS;   // 100000
    const int e = in_sizes[1];              // 1600000

    float *h, *el, *er;
    int *rowptr, *cnt, *csrc, *bsum;
    __nv_bfloat16 *x2h, *x2l, *w1h, *w1l, *w2h, *w2l;
    cudaGetSymbolAddress((void**)&h,      g_h);
    cudaGetSymbolAddress((void**)&el,     g_el);
    cudaGetSymbolAddress((void**)&er,     g_er);
    cudaGetSymbolAddress((void**)&rowptr, g_rowptr);
    cudaGetSymbolAddress((void**)&cnt,    g_cnt);
    cudaGetSymbolAddress((void**)&csrc,   g_csrc);
    cudaGetSymbolAddress((void**)&bsum,   g_bsum);
    cudaGetSymbolAddress((void**)&x2h,    g_x2h);
    cudaGetSymbolAddress((void**)&x2l,    g_x2l);
    cudaGetSymbolAddress((void**)&w1h,    g_w1h);
    cudaGetSymbolAddress((void**)&w1l,    g_w1l);
    cudaGetSymbolAddress((void**)&w2h,    g_w2h);
    cudaGetSymbolAddress((void**)&w2l,    g_w2l);

    const int TPB = 256;
    const int eblocks = (e + TPB - 1) / TPB;
    const int nwarp_blocks = (n * 32 + TPB - 1) / TPB;
    const int tc_blocks = (n + 127) / 128;
    const int scan_blocks = (n + SCAN_B - 1) / SCAN_B;   // 98
    const int SMEM_TC = 1024 + 128 * 132 * 4 + 256;

    cudaFuncSetAttribute((const void*)gemm_mma<IN_FEATS, false>,
                         cudaFuncAttributeMaxDynamicSharedMemorySize, SMEM_TC);
    cudaFuncSetAttribute((const void*)gemm_mma<HID, true>,
                         cudaFuncAttributeMaxDynamicSharedMemorySize, SMEM_TC);

    // weight pre-split (once per call, tiny)
    split_kernel<<<(HID * IN_FEATS / 4 + 255) / 256, 256>>>(W1, w1h, w1l, HID * IN_FEATS / 4);
    split_kernel<<<(HID * HID / 4 + 255) / 256, 256>>>(W2, w2h, w2l, HID * HID / 4);

    // CSR build (by dst) — decoupled parallel scan
    cudaMemsetAsync(cnt, 0, (size_t)(n + 1) * sizeof(int));
    hist_kernel<<<eblocks, TPB>>>(dst, cnt, e);
    blocksum_kernel<<<scan_blocks, SCAN_B>>>(cnt, bsum, n);
    scan_partials_kernel<<<1, 256>>>(bsum, scan_blocks);
    scan_apply_kernel<<<scan_blocks, SCAN_B>>>(cnt, bsum, rowptr, n);
    fill_kernel<<<eblocks, TPB>>>(src, dst, cnt, csrc, e);

    // ---- layer 1 ----
    gemm_mma<IN_FEATS, false><<<tc_blocks, TPB, SMEM_TC>>>(
        features, nullptr, nullptr, w1h, w1l, al1, ar1, h, el, er, n);
    attn_agg<true, true><<<nwarp_blocks, TPB>>>(
        rowptr, csrc, el, er, h, b1, nullptr, x2h, x2l, n);

    // ---- layer 2 ----
    gemm_mma<HID, true><<<tc_blocks, TPB, SMEM_TC>>>(
        nullptr, x2h, x2l, w2h, w2l, al2, ar2, h, el, er, n);
    attn_agg<false, false><<<nwarp_blocks, TPB>>>(
        rowptr, csrc, el, er, h, b2, out, nullptr, nullptr, n);
}